// round 11
// baseline (speedup 1.0000x reference)
#include <cuda_runtime.h>
#include <cuda_fp16.h>
#include <cstdint>

#define DI __device__ __forceinline__

static constexpr int HDIM   = 1024;
static constexpr int BATCH  = 8192;
static constexpr int BM     = 128;   // batch rows per CTA
static constexpr int BN     = 32;    // gate cols per CTA
static constexpr int NTH    = 256;   // 8 warps: 4 (m) x 2 (n)
static constexpr int NSTAGE = 48;    // 16 att + 16 input + 16 hx K=64-stages
static constexpr int RING   = 3;     // 3-deep ring -> 96KB -> 2 CTAs/SM

// K=64 fp16 stage buffer: A 128x64 (16KB) + B 4x32x64 (16KB); 128B rows
static constexpr int ABYTES = BM * 128;        // 16384
static constexpr int BUFB   = ABYTES + 16384;  // 32768
static constexpr int SMEMB  = RING * BUFB;     // 98304

// fp16 scratch (u32 element offsets; 2 halves per u32)
static constexpr size_t OFF_ATT  = 0;
static constexpr size_t OFF_INP  = 4194304;
static constexpr size_t OFF_HX   = 8388608;
static constexpr size_t OFF_WATT = 12582912;
static constexpr size_t OFF_WIH  = 13631488;
static constexpr size_t OFF_WHH  = 15728640;
static constexpr size_t CVT_TOTAL = 17825792;   // ~71.3 MB

__device__ uint32_t g_cvt[CVT_TOTAL];

DI float sigmf(float x) { return 1.0f / (1.0f + __expf(-x)); }

DI uint32_t smem_u32(const void* p) {
    uint32_t r;
    asm("{ .reg .u64 t; cvta.to.shared.u64 t, %1; cvt.u32.u64 %0, t; }" : "=r"(r) : "l"(p));
    return r;
}
DI void cp16(uint32_t sdst, const uint32_t* gsrc) {
    asm volatile("cp.async.cg.shared.global [%0], [%1], 16;" :: "r"(sdst), "l"(gsrc));
}
DI void cp_commit() { asm volatile("cp.async.commit_group;" ::: "memory"); }
template <int N>
DI void cp_wait() { asm volatile("cp.async.wait_group %0;" :: "n"(N) : "memory"); }

DI void ldsm4(uint32_t* r, uint32_t addr) {
    asm volatile("ldmatrix.sync.aligned.m8n8.x4.shared.b16 {%0,%1,%2,%3}, [%4];"
                 : "=r"(r[0]), "=r"(r[1]), "=r"(r[2]), "=r"(r[3]) : "r"(addr));
}
DI void mma16(float* d, const uint32_t* a, const uint32_t* b) {
    asm volatile(
        "mma.sync.aligned.m16n8k16.row.col.f32.f16.f16.f32 "
        "{%0,%1,%2,%3}, {%4,%5,%6,%7}, {%8,%9}, {%0,%1,%2,%3};"
        : "+f"(d[0]), "+f"(d[1]), "+f"(d[2]), "+f"(d[3])
        : "r"(a[0]), "r"(a[1]), "r"(a[2]), "r"(a[3]), "r"(b[0]), "r"(b[1]));
}

// ---- prepass: fp32 -> fp16(RN) bulk convert, single launch (6 segments) ----
__global__ void cvt_all_kernel(const float4* s_att, const float4* s_inp, const float4* s_hx,
                               const float4* s_watt, const float4* s_wih, const float4* s_whh)
{
    const int seg = blockIdx.y;
    const float4* src;
    uint2* dst;
    int n4;
    uint32_t* g = g_cvt;
    switch (seg) {
        case 0: src = s_att;  dst = (uint2*)(g + OFF_ATT);  n4 = 2097152; break;
        case 1: src = s_inp;  dst = (uint2*)(g + OFF_INP);  n4 = 2097152; break;
        case 2: src = s_hx;   dst = (uint2*)(g + OFF_HX);   n4 = 2097152; break;
        case 3: src = s_watt; dst = (uint2*)(g + OFF_WATT); n4 = 524288;  break;
        case 4: src = s_wih;  dst = (uint2*)(g + OFF_WIH);  n4 = 1048576; break;
        default: src = s_whh; dst = (uint2*)(g + OFF_WHH);  n4 = 1048576; break;
    }
    int i = blockIdx.x * blockDim.x + threadIdx.x;
    int stride = gridDim.x * blockDim.x;
    for (; i < n4; i += stride) {
        float4 v = __ldg(src + i);
        __half2 lo = __float22half2_rn(make_float2(v.x, v.y));
        __half2 hi = __float22half2_rn(make_float2(v.z, v.w));
        dst[i] = make_uint2(*(const uint32_t*)&lo, *(const uint32_t*)&hi);
    }
}

// ---- main kernel ----
// stages 0..15 : A=att,   B=watt (2 att blocks)
// stages 16..31: A=input, B=wih  (4 gate blocks)
// stages 32..47: A=hx,    B=whh  (4 gate blocks)
DI void issue_stage(int s, uint32_t buf, uint32_t sA, uint32_t sB,
                    const uint32_t* Arow, const uint32_t* Brow)
{
    const int seg = s >> 4;
    const int k0  = (s & 15) << 5;                 // u32 offset within 512-u32 row
    const uint32_t bsel = (seg == 0) ? 0u : ((seg == 1) ? 1048576u : 3145728u);
    const uint32_t* Ap = Arow + (size_t)seg * 4194304 + k0;
    const uint32_t* Bp = Brow + bsel + k0;
    const uint32_t dA = buf + sA;
    const uint32_t dB = buf + sB;
    cp16(dA,         Ap);                // rows 0-31
    cp16(dA + 4096,  Ap + 16384);        // rows 32-63
    cp16(dA + 8192,  Ap + 32768);        // rows 64-95
    cp16(dA + 12288, Ap + 49152);        // rows 96-127
    cp16(dB,         Bp);                // gate block 0
    cp16(dB + 4096,  Bp + 524288);       // gate block 1
    if (seg != 0) {
        cp16(dB + 8192,  Bp + 1048576);  // gate block 2
        cp16(dB + 12288, Bp + 1572864);  // gate block 3
    }
    cp_commit();
}

// phase-1 compute (2 blocks): full cross-k16 fragment double-buffering
DI void compute_stage2(uint32_t buf, uint32_t pA0, uint32_t pA1, uint32_t pB,
                       float c[][2][2][4])
{
    const uint32_t aA0 = buf + pA0;
    const uint32_t aA1 = buf + pA1;
    const uint32_t bB  = buf + pB;
    uint32_t a0[2][4], a1[2][4], b0[2][4], b1[2][4];
    ldsm4(b0[0], bB);
    ldsm4(b1[0], bB + 4096);
    ldsm4(a0[0], aA0);
    ldsm4(a1[0], aA1);
    #pragma unroll
    for (int k16 = 0; k16 < 4; ++k16) {
        const int cur = k16 & 1, nxt = cur ^ 1;
        if (k16 < 3) {   // prefetch next k16 BEFORE this k16's MMAs
            const uint32_t kx = (uint32_t)((k16 + 1) << 5);
            ldsm4(b0[nxt], bB ^ kx);
            ldsm4(b1[nxt], (bB + 4096) ^ kx);
            ldsm4(a0[nxt], aA0 ^ kx);
            ldsm4(a1[nxt], aA1 ^ kx);
        }
        mma16(c[0][0][0], a0[cur], b0[cur]);
        mma16(c[0][0][1], a0[cur], b0[cur] + 2);
        mma16(c[0][1][0], a1[cur], b0[cur]);
        mma16(c[0][1][1], a1[cur], b0[cur] + 2);
        mma16(c[1][0][0], a0[cur], b1[cur]);
        mma16(c[1][0][1], a0[cur], b1[cur] + 2);
        mma16(c[1][1][0], a1[cur], b1[cur]);
        mma16(c[1][1][1], a1[cur], b1[cur] + 2);
    }
}

// phase-2 compute (4 blocks): batch all 6 ldsm per k16 before the 16 MMAs
DI void compute_stage4(uint32_t buf, uint32_t pA0, uint32_t pA1, uint32_t pB,
                       float c[][2][2][4])
{
    const uint32_t aA0 = buf + pA0;
    const uint32_t aA1 = buf + pA1;
    const uint32_t bB  = buf + pB;
    #pragma unroll
    for (int k16 = 0; k16 < 4; ++k16) {
        const uint32_t kx = (uint32_t)(k16 << 5);
        uint32_t b0[4], b1[4], b2[4], b3[4], a0[4], a1[4];
        ldsm4(b0, bB ^ kx);
        ldsm4(b1, (bB + 4096) ^ kx);
        ldsm4(b2, (bB + 8192) ^ kx);
        ldsm4(b3, (bB + 12288) ^ kx);
        ldsm4(a0, aA0 ^ kx);
        ldsm4(a1, aA1 ^ kx);
        mma16(c[0][0][0], a0, b0);
        mma16(c[0][0][1], a0, b0 + 2);
        mma16(c[0][1][0], a1, b0);
        mma16(c[0][1][1], a1, b0 + 2);
        mma16(c[1][0][0], a0, b1);
        mma16(c[1][0][1], a0, b1 + 2);
        mma16(c[1][1][0], a1, b1);
        mma16(c[1][1][1], a1, b1 + 2);
        mma16(c[2][0][0], a0, b2);
        mma16(c[2][0][1], a0, b2 + 2);
        mma16(c[2][1][0], a1, b2);
        mma16(c[2][1][1], a1, b2 + 2);
        mma16(c[3][0][0], a0, b3);
        mma16(c[3][0][1], a0, b3 + 2);
        mma16(c[3][1][0], a1, b3);
        mma16(c[3][1][1], a1, b3 + 2);
    }
}

__global__ __launch_bounds__(NTH, 2)
void lstm_att_kernel(const float* __restrict__ cx,
                     const float* __restrict__ bih, const float* __restrict__ bhh,
                     const float* __restrict__ batt,
                     float* __restrict__ out)
{
    extern __shared__ char smem[];
    const int tid  = threadIdx.x;
    const int wid  = tid >> 5;
    const int lane = tid & 31;
    const int wm = wid >> 1, wn = wid & 1;
    const int n0 = blockIdx.x * BN;
    const int m0 = blockIdx.y * BM;
    const uint32_t sbase = smem_u32(smem);

    // ---- producer addressing (128B rows, chunk ^ row&7 swizzle) ----
    const int tid8 = tid >> 3;
    const int cc   = tid & 7;
    const uint32_t sw   = (uint32_t)((cc ^ (tid8 & 7)) << 4);
    const uint32_t sAof = (uint32_t)(tid8 * 128) + sw;
    const uint32_t sBof = (uint32_t)ABYTES + (uint32_t)(tid8 * 128) + sw;
    const uint32_t* Arow = g_cvt + OFF_ATT  + (size_t)(m0 + tid8) * 512 + cc * 4;
    const uint32_t* Brow = g_cvt + OFF_WATT + (size_t)(n0 + tid8) * 512 + cc * 4;

    // ---- consumer (ldsm) addressing, XOR-folded ----
    const int arow = wm * 32 + (lane & 15);
    const int ahi  = (lane >> 4) & 1;
    const int ax   = arow & 7;
    const uint32_t pA0 = (uint32_t)(arow * 128)        ^ (uint32_t)(((ahi ^ ax) & 7) << 4);
    const uint32_t pA1 = (uint32_t)((arow + 16) * 128) ^ (uint32_t)(((ahi ^ ax) & 7) << 4);
    const int brow = wn * 16 + (lane & 7) + ((lane & 16) >> 1);
    const int bhi  = (lane >> 3) & 1;
    const int bx   = brow & 7;
    const uint32_t pB  = (uint32_t)ABYTES + ((uint32_t)(brow * 128) ^ (uint32_t)(((bhi ^ bx) & 7) << 4));

    issue_stage(0, sbase,        sAof, sBof, Arow, Brow);
    issue_stage(1, sbase + BUFB, sAof, sBof, Arow, Brow);

    int ring_c = 0, ring_i = 2;

    // ===== phase 1: att segment (stages 0..15), 32 accum regs =====
    float ca[2][2][2][4];
    #pragma unroll
    for (int b = 0; b < 2; ++b)
        #pragma unroll
        for (int mf = 0; mf < 2; ++mf)
            #pragma unroll
            for (int nf = 0; nf < 2; ++nf)
                #pragma unroll
                for (int i = 0; i < 4; ++i) ca[b][mf][nf][i] = 0.0f;

    for (int s = 0; s < 16; ++s) {
        cp_wait<1>();
        __syncthreads();
        issue_stage(s + 2, sbase + ring_i * BUFB, sAof, sBof, Arow, Brow);
        compute_stage2(sbase + ring_c * BUFB, pA0, pA1, pB, ca);
        ring_c = (ring_c == RING - 1) ? 0 : ring_c + 1;
        ring_i = (ring_i == RING - 1) ? 0 : ring_i + 1;
    }

    // ---- collapse att gates to 16 partials: p = sigmoid(ia) * tanh(aa) ----
    const int gid = lane >> 2, tig = lane & 3;
    float p[2][2][4];
    {
        float bt0[2][2], bt1[2][2];
        #pragma unroll
        for (int nf = 0; nf < 2; ++nf) {
            const int col = n0 + wn * 16 + nf * 8 + tig * 2;
            float2 t0 = __ldg((const float2*)(batt + col));
            float2 t1 = __ldg((const float2*)(batt + 1024 + col));
            bt0[nf][0] = t0.x; bt0[nf][1] = t0.y;
            bt1[nf][0] = t1.x; bt1[nf][1] = t1.y;
        }
        #pragma unroll
        for (int mf = 0; mf < 2; ++mf)
            #pragma unroll
            for (int nf = 0; nf < 2; ++nf)
                #pragma unroll
                for (int i = 0; i < 4; ++i) {
                    const int q = i & 1;
                    float ia = sigmf(ca[0][mf][nf][i] + bt0[nf][q]);
                    float aa = tanhf(ca[1][mf][nf][i] + bt1[nf][q]);
                    p[mf][nf][i] = ia * aa;
                }
    }

    // ===== phase 2: input + hx segments (stages 16..47), 64+16 accum regs =====
    float cm[4][2][2][4];
    #pragma unroll
    for (int b = 0; b < 4; ++b)
        #pragma unroll
        for (int mf = 0; mf < 2; ++mf)
            #pragma unroll
            for (int nf = 0; nf < 2; ++nf)
                #pragma unroll
                for (int i = 0; i < 4; ++i) cm[b][mf][nf][i] = 0.0f;

    for (int s = 16; s < NSTAGE; ++s) {
        cp_wait<1>();
        __syncthreads();
        if (s + 2 < NSTAGE)
            issue_stage(s + 2, sbase + ring_i * BUFB, sAof, sBof, Arow, Brow);
        else
            cp_commit();
        compute_stage4(sbase + ring_c * BUFB, pA0, pA1, pB, cm);
        ring_c = (ring_c == RING - 1) ? 0 : ring_c + 1;
        ring_i = (ring_i == RING - 1) ? 0 : ring_i + 1;
    }

    // ---- fused LSTM epilogue ----
    const size_t cy_base = (size_t)BATCH * HDIM;
    #pragma unroll
    for (int mf = 0; mf < 2; ++mf) {
        #pragma unroll
        for (int i2 = 0; i2 < 2; ++i2) {
            const int row = m0 + wm * 32 + mf * 16 + gid + i2 * 8;
            #pragma unroll
            for (int nf = 0; nf < 2; ++nf) {
                const int col = n0 + wn * 16 + nf * 8 + tig * 2;
                float2 cx2 = __ldg((const float2*)(cx + (size_t)row * HDIM + col));
                float hyv[2], cyv[2];
                #pragma unroll
                for (int q = 0; q < 2; ++q) {
                    const int i = i2 * 2 + q;
                    const int n = col + q;
                    float gi  = cm[0][mf][nf][i] + __ldg(bih + n)        + __ldg(bhh + n);
                    float gf  = cm[1][mf][nf][i] + __ldg(bih + 1024 + n) + __ldg(bhh + 1024 + n);
                    float gc  = cm[2][mf][nf][i] + __ldg(bih + 2048 + n) + __ldg(bhh + 2048 + n);
                    float go  = cm[3][mf][nf][i] + __ldg(bih + 3072 + n) + __ldg(bhh + 3072 + n);
                    float i_  = sigmf(gi);
                    float f_  = sigmf(gf);
                    float c_  = tanhf(gc);
                    float o_  = sigmf(go);
                    float cv  = f_ * ((q == 0) ? cx2.x : cx2.y) + i_ * c_ + p[mf][nf][i];
                    cyv[q] = cv;
                    hyv[q] = o_ * tanhf(cv);
                }
                *(float2*)(out + (size_t)row * HDIM + col)           = make_float2(hyv[0], hyv[1]);
                *(float2*)(out + cy_base + (size_t)row * HDIM + col) = make_float2(cyv[0], cyv[1]);
            }
        }
    }
}

extern "C" void kernel_launch(void* const* d_in, const int* in_sizes, int n_in,
                              void* d_out, int out_size)
{
    (void)in_sizes; (void)n_in; (void)out_size;
    const float* inp  = (const float*)d_in[0];
    const float* hx   = (const float*)d_in[1];
    const float* cx   = (const float*)d_in[2];
    const float* att  = (const float*)d_in[3];
    const float* wih  = (const float*)d_in[4];
    const float* whh  = (const float*)d_in[5];
    const float* bih  = (const float*)d_in[6];
    const float* bhh  = (const float*)d_in[7];
    const float* watt = (const float*)d_in[8];
    const float* batt = (const float*)d_in[9];
    float* out = (float*)d_out;

    dim3 cgrid(1024, 6);
    cvt_all_kernel<<<cgrid, 256>>>((const float4*)att, (const float4*)inp,
                                   (const float4*)hx,  (const float4*)watt,
                                   (const float4*)wih, (const float4*)whh);

    cudaFuncSetAttribute(lstm_att_kernel,
                         cudaFuncAttributeMaxDynamicSharedMemorySize, SMEMB);
    dim3 grid(HDIM / BN, BATCH / BM);
    lstm_att_kernel<<<grid, NTH, SMEMB>>>(cx, bih, bhh, batt, out);
}